// round 5
// baseline (speedup 1.0000x reference)
#include <cuda_runtime.h>
#include <cstdint>

#define NPTS     16384
#define ATILES   16
#define APERTILE 1024                 // A points per tile = THREADS * KA
#define NCHUNK   128
#define CHUNK    128                  // B points staged per block
#define THREADS  256
#define KA       4
#define RBLOCKS  128                  // reduce-kernel blocks

// ---------------- persistent scratch (no allocations allowed) ----------------
__device__ float g_scratch[2][NCHUNK][NPTS];   // per-chunk partial min scores (16.8 MB)
__device__ float g_partial[RBLOCKS];           // per-reduce-block distance sums

// ---------------- packed f32x2 helpers ----------------
__device__ __forceinline__ unsigned long long pack2(float lo, float hi) {
    unsigned long long r;
    asm("mov.b64 %0, {%1, %2};" : "=l"(r) : "f"(lo), "f"(hi));
    return r;
}
__device__ __forceinline__ unsigned long long fma2(unsigned long long a,
                                                   unsigned long long b,
                                                   unsigned long long c) {
    unsigned long long d;
    asm("fma.rn.f32x2 %0, %1, %2, %3;" : "=l"(d) : "l"(a), "l"(b), "l"(c));
    return d;
}
__device__ __forceinline__ void unpack2(unsigned long long v, float& lo, float& hi) {
    asm("mov.b64 {%0, %1}, %2;" : "=f"(lo), "=f"(hi) : "l"(v));
}

#define POS_INF __int_as_float(0x7f800000)

// ---------------- kernel 1: main pairwise min-score ----------------
// grid = 2 dirs x 16 A-tiles x 128 B-chunks = 4096 blocks, 256 threads.
// Small units -> near-perfect SM load balance (4096 / (148*4) = 6.92 units per
// CTA-slot, tail loss ~1%). Each thread owns KA=4 A points; block stages+packs
// its 128-point B chunk into smem, then scans it with packed f32x2 FMA chains.
__global__ void __launch_bounds__(THREADS)
main_kernel(const float* __restrict__ pred, const float* __restrict__ targ) {
    __shared__ __align__(16) float sB[4][CHUNK];    // bx', by', bz', |b|^2 (2 KB)

    const int bid    = blockIdx.x;
    const int dir    = bid >> 11;          // 0: A=pred,B=targ   1: A=targ,B=pred
    const int rem    = bid & 2047;
    const int a_tile = rem >> 7;
    const int chunk  = rem & 127;
    const int tid    = threadIdx.x;

    const float* __restrict__ araw = dir ? targ : pred;
    const float* __restrict__ braw = dir ? pred : targ;
    const int jbase = chunk * CHUNK;

    // ---- stage + pack B chunk from raw coords ----
    if (tid < CHUNK) {
        const int j = jbase + tid;
        float x = braw[3 * j + 0];
        float y = braw[3 * j + 1];
        float z = braw[3 * j + 2];
        sB[0][tid] = -2.0f * x;
        sB[1][tid] = -2.0f * y;
        sB[2][tid] = -2.0f * z;
        sB[3][tid] = x * x + y * y + z * z;
    }

    // ---- load A points, replicate into both packed halves ----
    const int a0 = a_tile * APERTILE + tid;
    unsigned long long ax2[KA], ay2[KA], az2[KA];
    float mlo[KA], mhi[KA];
#pragma unroll
    for (int k = 0; k < KA; k++) {
        const int ai = a0 + k * THREADS;
        float x = araw[3 * ai + 0];
        float y = araw[3 * ai + 1];
        float z = araw[3 * ai + 2];
        ax2[k] = pack2(x, x);
        ay2[k] = pack2(y, y);
        az2[k] = pack2(z, z);
        mlo[k] = POS_INF;
        mhi[k] = POS_INF;
    }
    __syncthreads();

    // ---- main loop: 4 B points per iteration, unrolled x8 ----
    // Immediate-offset LDS + amortized loop overhead keep the alu pipe quiet.
#pragma unroll 8
    for (int j = 0; j < CHUNK; j += 4) {
        ulonglong2 vx = *(const ulonglong2*)&sB[0][j];
        ulonglong2 vy = *(const ulonglong2*)&sB[1][j];
        ulonglong2 vz = *(const ulonglong2*)&sB[2][j];
        ulonglong2 vc = *(const ulonglong2*)&sB[3][j];
#pragma unroll
        for (int k = 0; k < KA; k++) {
            unsigned long long s01 =
                fma2(ax2[k], vx.x, fma2(ay2[k], vy.x, fma2(az2[k], vz.x, vc.x)));
            unsigned long long s23 =
                fma2(ax2[k], vx.y, fma2(ay2[k], vy.y, fma2(az2[k], vz.y, vc.y)));
            float s0, s1, s2, s3;
            unpack2(s01, s0, s1);
            unpack2(s23, s2, s3);
            mlo[k] = fminf(mlo[k], fminf(s0, s2));
            mhi[k] = fminf(mhi[k], fminf(s1, s3));
        }
    }

#pragma unroll
    for (int k = 0; k < KA; k++) {
        g_scratch[dir][chunk][a0 + k * THREADS] = fminf(mlo[k], mhi[k]);
    }
}

// ---------------- kernel 2: per-point reduce + sqrt + block partials ----------
// 128 blocks x 256 threads; blocks [0,64) = dir 0, [64,128) = dir 1.
__global__ void __launch_bounds__(THREADS)
reduce_kernel(const float* __restrict__ pred, const float* __restrict__ targ) {
    const int dir = blockIdx.x >> 6;
    const int a   = (blockIdx.x & 63) * THREADS + threadIdx.x;
    const float* __restrict__ araw = dir ? targ : pred;

    float m = POS_INF;
#pragma unroll 16
    for (int c = 0; c < NCHUNK; c++) m = fminf(m, g_scratch[dir][c][a]);

    float x = araw[3 * a + 0];
    float y = araw[3 * a + 1];
    float z = araw[3 * a + 2];
    float ca = x * x + y * y + z * z;
    float d = sqrtf(fmaxf(ca + m, 0.0f));

    __shared__ float sRed[THREADS / 32];
#pragma unroll
    for (int s = 16; s > 0; s >>= 1)
        d += __shfl_xor_sync(0xFFFFFFFFu, d, s);
    if ((threadIdx.x & 31) == 0) sRed[threadIdx.x >> 5] = d;
    __syncthreads();
    if (threadIdx.x == 0) {
        float t = 0.0f;
#pragma unroll
        for (int w = 0; w < THREADS / 32; w++) t += sRed[w];
        g_partial[blockIdx.x] = t;
    }
}

// ---------------- kernel 3: final sum ----------------
__global__ void final_kernel(float* __restrict__ out) {
    float v = (threadIdx.x < RBLOCKS) ? g_partial[threadIdx.x] : 0.0f;
#pragma unroll
    for (int s = 16; s > 0; s >>= 1)
        v += __shfl_xor_sync(0xFFFFFFFFu, v, s);
    __shared__ float sRed[4];
    if ((threadIdx.x & 31) == 0) sRed[threadIdx.x >> 5] = v;
    __syncthreads();
    if (threadIdx.x == 0) {
        out[0] = (sRed[0] + sRed[1] + sRed[2] + sRed[3]) * (1.0f / (float)NPTS);
    }
}

// ---------------- launch ----------------
extern "C" void kernel_launch(void* const* d_in, const int* in_sizes, int n_in,
                              void* d_out, int out_size) {
    const float* pred = (const float*)d_in[0];
    const float* targ = (const float*)d_in[1];
    float* out = (float*)d_out;

    main_kernel<<<2 * ATILES * NCHUNK, THREADS>>>(pred, targ);
    reduce_kernel<<<RBLOCKS, THREADS>>>(pred, targ);
    final_kernel<<<1, RBLOCKS>>>(out);
}

// round 6
// speedup vs baseline: 1.0261x; 1.0261x over previous
#include <cuda_runtime.h>
#include <cstdint>

#define NPTS     16384
#define ATILES   16
#define APERTILE 1024                 // A points per tile = MTHREADS * KA
#define NCHUNK   128
#define CHUNK    128                  // B points staged per block
#define MTHREADS 128                  // main kernel block size
#define KA       8                    // A points per thread (16 indep FMA chains)
#define RTHREADS 256
#define RBLOCKS  128                  // reduce-kernel blocks

// ---------------- persistent scratch (no allocations allowed) ----------------
__device__ float g_scratch[2][NCHUNK][NPTS];   // per-chunk partial min scores (16.8 MB)
__device__ float g_partial[RBLOCKS];           // per-reduce-block distance sums

// ---------------- packed f32x2 helpers ----------------
__device__ __forceinline__ unsigned long long pack2(float lo, float hi) {
    unsigned long long r;
    asm("mov.b64 %0, {%1, %2};" : "=l"(r) : "f"(lo), "f"(hi));
    return r;
}
__device__ __forceinline__ unsigned long long fma2(unsigned long long a,
                                                   unsigned long long b,
                                                   unsigned long long c) {
    unsigned long long d;
    asm("fma.rn.f32x2 %0, %1, %2, %3;" : "=l"(d) : "l"(a), "l"(b), "l"(c));
    return d;
}
__device__ __forceinline__ void unpack2(unsigned long long v, float& lo, float& hi) {
    asm("mov.b64 {%0, %1}, %2;" : "=f"(lo), "=f"(hi) : "l"(v));
}

#define POS_INF __int_as_float(0x7f800000)

// ---------------- kernel 1: main pairwise min-score ----------------
// grid = 2 dirs x 16 A-tiles x 128 B-chunks = 4096 blocks, 128 threads.
// KA=8 A points per thread -> 16 independent 3-deep FFMA2 chains (96 fma-pipe
// cycles) behind every 4-LDS batch: LDS (29cy) and chain (12cy) latency are
// hidden WITHIN one warp instead of relying on occupancy.
__global__ void __launch_bounds__(MTHREADS)
main_kernel(const float* __restrict__ pred, const float* __restrict__ targ) {
    __shared__ __align__(16) float sB[4][CHUNK];    // bx', by', bz', |b|^2 (2 KB)

    const int bid    = blockIdx.x;
    const int dir    = bid >> 11;          // 0: A=pred,B=targ   1: A=targ,B=pred
    const int rem    = bid & 2047;
    const int a_tile = rem >> 7;
    const int chunk  = rem & 127;
    const int tid    = threadIdx.x;

    const float* __restrict__ araw = dir ? targ : pred;
    const float* __restrict__ braw = dir ? pred : targ;
    const int jbase = chunk * CHUNK;

    // ---- stage + pack B chunk from raw coords (one point per thread) ----
    {
        const int j = jbase + tid;
        float x = braw[3 * j + 0];
        float y = braw[3 * j + 1];
        float z = braw[3 * j + 2];
        sB[0][tid] = -2.0f * x;
        sB[1][tid] = -2.0f * y;
        sB[2][tid] = -2.0f * z;
        sB[3][tid] = x * x + y * y + z * z;
    }

    // ---- load A points, replicate into both packed halves ----
    const int a0 = a_tile * APERTILE + tid;
    unsigned long long ax2[KA], ay2[KA], az2[KA];
    float mlo[KA], mhi[KA];
#pragma unroll
    for (int k = 0; k < KA; k++) {
        const int ai = a0 + k * MTHREADS;
        float x = araw[3 * ai + 0];
        float y = araw[3 * ai + 1];
        float z = araw[3 * ai + 2];
        ax2[k] = pack2(x, x);
        ay2[k] = pack2(y, y);
        az2[k] = pack2(z, z);
        mlo[k] = POS_INF;
        mhi[k] = POS_INF;
    }
    __syncthreads();

    // ---- main loop: 4 B points per iteration x 8 A points per thread ----
#pragma unroll 4
    for (int j = 0; j < CHUNK; j += 4) {
        ulonglong2 vx = *(const ulonglong2*)&sB[0][j];
        ulonglong2 vy = *(const ulonglong2*)&sB[1][j];
        ulonglong2 vz = *(const ulonglong2*)&sB[2][j];
        ulonglong2 vc = *(const ulonglong2*)&sB[3][j];
#pragma unroll
        for (int k = 0; k < KA; k++) {
            unsigned long long s01 =
                fma2(ax2[k], vx.x, fma2(ay2[k], vy.x, fma2(az2[k], vz.x, vc.x)));
            unsigned long long s23 =
                fma2(ax2[k], vx.y, fma2(ay2[k], vy.y, fma2(az2[k], vz.y, vc.y)));
            float s0, s1, s2, s3;
            unpack2(s01, s0, s1);
            unpack2(s23, s2, s3);
            mlo[k] = fminf(mlo[k], fminf(s0, s2));
            mhi[k] = fminf(mhi[k], fminf(s1, s3));
        }
    }

#pragma unroll
    for (int k = 0; k < KA; k++) {
        g_scratch[dir][chunk][a0 + k * MTHREADS] = fminf(mlo[k], mhi[k]);
    }
}

// ---------------- kernel 2: per-point reduce + sqrt + block partials ----------
// 128 blocks x 256 threads; blocks [0,64) = dir 0, [64,128) = dir 1.
__global__ void __launch_bounds__(RTHREADS)
reduce_kernel(const float* __restrict__ pred, const float* __restrict__ targ) {
    const int dir = blockIdx.x >> 6;
    const int a   = (blockIdx.x & 63) * RTHREADS + threadIdx.x;
    const float* __restrict__ araw = dir ? targ : pred;

    float m = POS_INF;
#pragma unroll 16
    for (int c = 0; c < NCHUNK; c++) m = fminf(m, g_scratch[dir][c][a]);

    float x = araw[3 * a + 0];
    float y = araw[3 * a + 1];
    float z = araw[3 * a + 2];
    float ca = x * x + y * y + z * z;
    float d = sqrtf(fmaxf(ca + m, 0.0f));

    __shared__ float sRed[RTHREADS / 32];
#pragma unroll
    for (int s = 16; s > 0; s >>= 1)
        d += __shfl_xor_sync(0xFFFFFFFFu, d, s);
    if ((threadIdx.x & 31) == 0) sRed[threadIdx.x >> 5] = d;
    __syncthreads();
    if (threadIdx.x == 0) {
        float t = 0.0f;
#pragma unroll
        for (int w = 0; w < RTHREADS / 32; w++) t += sRed[w];
        g_partial[blockIdx.x] = t;
    }
}

// ---------------- kernel 3: final sum ----------------
__global__ void final_kernel(float* __restrict__ out) {
    float v = (threadIdx.x < RBLOCKS) ? g_partial[threadIdx.x] : 0.0f;
#pragma unroll
    for (int s = 16; s > 0; s >>= 1)
        v += __shfl_xor_sync(0xFFFFFFFFu, v, s);
    __shared__ float sRed[4];
    if ((threadIdx.x & 31) == 0) sRed[threadIdx.x >> 5] = v;
    __syncthreads();
    if (threadIdx.x == 0) {
        out[0] = (sRed[0] + sRed[1] + sRed[2] + sRed[3]) * (1.0f / (float)NPTS);
    }
}

// ---------------- launch ----------------
extern "C" void kernel_launch(void* const* d_in, const int* in_sizes, int n_in,
                              void* d_out, int out_size) {
    const float* pred = (const float*)d_in[0];
    const float* targ = (const float*)d_in[1];
    float* out = (float*)d_out;

    main_kernel<<<2 * ATILES * NCHUNK, MTHREADS>>>(pred, targ);
    reduce_kernel<<<RBLOCKS, RTHREADS>>>(pred, targ);
    final_kernel<<<1, RBLOCKS>>>(out);
}